// round 6
// baseline (speedup 1.0000x reference)
#include <cuda_runtime.h>
#include <cuda_bf16.h>
#include <math.h>
#include <stdint.h>

#define NN 2048
#define BB 256
#define DD 512
#define MAXIT 300

// ---- solve: 16 m-tiles x 8 k-splits, W chunk resident in SMEM --------------
#define SB 128
#define MT 128           // rows per CTA
#define KS 256           // k per CTA (resident W chunk: 128x256 hi+lo = 128KB)
#define O_WBYTES 131072  // W chunk bytes
#define BSTG 40960       // one B stage: 256 j x 80B x 2 prec
#define BPREC 20480
#define DYN_SMEM (O_WBYTES + 2*BSTG + 256)

// ---- build_w tiling ---------------------------------------------------------
#define WNSTG 3
#define WMAT (128*128)
#define WSTG (4*WMAT)
#define WDYN (WNSTG*WSTG + 128)
#define KC 64
#define NKC (NN/KC)

__device__ __nv_bfloat16 g_Whi[NN*NN];
__device__ __nv_bfloat16 g_Wlo[NN*NN];
__device__ __nv_bfloat16 g_Athi[NN*NN];
__device__ __nv_bfloat16 g_Atlo[NN*NN];
__device__ float         g_Vx[NN*BB];       // [i][j]
__device__ float         g_zf[NN*BB];       // fp32 z state, [i][j]
__device__ __nv_bfloat16 g_zbh[2][BB*NN];   // z hi split, [j][k]
__device__ __nv_bfloat16 g_zbl[2][BB*NN];   // z lo split
__device__ float         g_part[(long)SB*MT*BB];  // 16MB fp32 partials
__device__ double g_nd[3][2];
__device__ unsigned g_arrive, g_release;

__device__ __forceinline__ uint32_t smem_u32(const void* p) {
    uint32_t a;
    asm("{ .reg .u64 t; cvta.to.shared.u64 t, %1; cvt.u32.u64 %0, t; }" : "=r"(a) : "l"(p));
    return a;
}
__device__ __forceinline__ void cp16(uint32_t dst, const void* src) {
    asm volatile("cp.async.cg.shared.global [%0], [%1], 16;" :: "r"(dst), "l"(src) : "memory");
}
#define CP_COMMIT() asm volatile("cp.async.commit_group;" ::: "memory")
#define CP_WAIT(n)  asm volatile("cp.async.wait_group %0;" :: "n"(n) : "memory")
__device__ __forceinline__ void ldsm4(uint32_t* r, uint32_t a) {
    asm volatile("ldmatrix.sync.aligned.m8n8.x4.shared.b16 {%0,%1,%2,%3}, [%4];"
                 : "=r"(r[0]), "=r"(r[1]), "=r"(r[2]), "=r"(r[3]) : "r"(a));
}
__device__ __forceinline__ void mma16816(float* c, const uint32_t* a, uint32_t b0, uint32_t b1) {
    asm volatile("mma.sync.aligned.m16n8k16.row.col.f32.bf16.bf16.f32 "
                 "{%0,%1,%2,%3}, {%4,%5,%6,%7}, {%8,%9}, {%0,%1,%2,%3};"
                 : "+f"(c[0]), "+f"(c[1]), "+f"(c[2]), "+f"(c[3])
                 : "r"(a[0]), "r"(a[1]), "r"(a[2]), "r"(a[3]), "r"(b0), "r"(b1));
}

__global__ void init_kernel() {
    int idx = blockIdx.x * blockDim.x + threadIdx.x;
    if (idx < BB * NN) {
        g_zbh[0][idx] = __float2bfloat16(0.0f);
        g_zbl[0][idx] = __float2bfloat16(0.0f);
        g_zf[idx] = 0.0f;
    }
    if (idx == 0) {
        for (int i = 0; i < 3; i++) { g_nd[i][0] = 0.0; g_nd[i][1] = 0.0; }
        g_arrive = 0u; g_release = 0u;
    }
}

// At[i][k] = A[k][i], split bf16 hi/lo
__global__ void __launch_bounds__(256) split_at_kernel(const float* __restrict__ A) {
    __shared__ float t[32][33];
    const int i0 = blockIdx.x * 32, k0 = blockIdx.y * 32;
    const int lx = threadIdx.x & 31, ly = threadIdx.x >> 5;
#pragma unroll
    for (int r = 0; r < 32; r += 8)
        t[ly + r][lx] = A[(long)(k0 + ly + r) * NN + i0 + lx];
    __syncthreads();
#pragma unroll
    for (int r = 0; r < 32; r += 8) {
        const float v = t[lx][ly + r];
        const long o = (long)(i0 + ly + r) * NN + k0 + lx;
        __nv_bfloat16 hi = __float2bfloat16_rn(v);
        g_Athi[o] = hi;
        g_Atlo[o] = __float2bfloat16_rn(v - __bfloat162float(hi));
    }
}

// W = (1-m)I - At At^T + S - S^T  (bf16x3 mma), tile 128x128
__global__ void __launch_bounds__(256, 1) build_w_mma_kernel(const float* __restrict__ S,
                                                             const float* __restrict__ m_raw) {
    extern __shared__ __align__(16) char dsm[];
    const uint32_t sbase = (smem_u32(dsm) + 127u) & ~127u;
    const int tid = threadIdx.x, l = tid & 31, warp = tid >> 5;
    const int i0 = blockIdx.x * 128, j0 = blockIdx.y * 128;
    const int wm = (warp >> 2) * 64, wn = (warp & 3) * 32;
    const int r7 = l & 7;
    const int rowA = wm + r7 + ((l >> 3) & 1) * 8;
    const int kgA = (l >> 4) & 1;
    const int rowBb = wn + r7 + ((l >> 4) & 1) * 8;
    const int kgB = (l >> 3) & 1;
    const int ld_r = tid >> 3, ld_c = tid & 7;

    float c[4][4][4];
#pragma unroll
    for (int f = 0; f < 4; f++)
#pragma unroll
        for (int g = 0; g < 4; g++)
#pragma unroll
            for (int q = 0; q < 4; q++) c[f][g][q] = 0.0f;

#define W_LOAD(stg, k0v) do {                                                 \
    const uint32_t sb_ = sbase + (stg) * WSTG;                                \
    _Pragma("unroll")                                                         \
    for (int rep = 0; rep < 4; rep++) {                                       \
        const int r_ = ld_r + rep * 32;                                       \
        const uint32_t d_ = (uint32_t)r_ * 128 + ((uint32_t)(ld_c ^ (r_ & 7)) << 4); \
        const long ga_ = (long)(i0 + r_) * NN + (k0v) + ld_c * 8;             \
        const long gb_ = (long)(j0 + r_) * NN + (k0v) + ld_c * 8;             \
        cp16(sb_ + 0*WMAT + d_, g_Athi + ga_);                                \
        cp16(sb_ + 1*WMAT + d_, g_Atlo + ga_);                                \
        cp16(sb_ + 2*WMAT + d_, g_Athi + gb_);                                \
        cp16(sb_ + 3*WMAT + d_, g_Atlo + gb_);                                \
    } } while (0)

#pragma unroll
    for (int s = 0; s < WNSTG - 1; s++) { W_LOAD(s, s * KC); CP_COMMIT(); }

    for (int kc = 0; kc < NKC; kc++) {
        CP_WAIT(WNSTG - 2);
        __syncthreads();
        if (kc + WNSTG - 1 < NKC) W_LOAD((kc + WNSTG - 1) % WNSTG, (kc + WNSTG - 1) * KC);
        CP_COMMIT();
        const uint32_t sb = sbase + (kc % WNSTG) * WSTG;
#pragma unroll
        for (int s4 = 0; s4 < 4; s4++) {
            const int kg0 = s4 * 2;
            const uint32_t swA = (uint32_t)((kg0 + kgA) ^ r7) << 4;
            const uint32_t swB = (uint32_t)((kg0 + kgB) ^ r7) << 4;
            uint32_t ah[4][4], al[4][4], bh[2][4], bl[2][4];
#pragma unroll
            for (int f = 0; f < 4; f++) {
                ldsm4(ah[f], sb + 0*WMAT + (uint32_t)(rowA + f * 16) * 128 + swA);
                ldsm4(al[f], sb + 1*WMAT + (uint32_t)(rowA + f * 16) * 128 + swA);
            }
#pragma unroll
            for (int g2 = 0; g2 < 2; g2++) {
                ldsm4(bh[g2], sb + 2*WMAT + (uint32_t)(rowBb + g2 * 16) * 128 + swB);
                ldsm4(bl[g2], sb + 3*WMAT + (uint32_t)(rowBb + g2 * 16) * 128 + swB);
            }
#pragma unroll
            for (int f = 0; f < 4; f++)
#pragma unroll
                for (int g2 = 0; g2 < 2; g2++) {
                    mma16816(c[f][g2*2+0], ah[f], bh[g2][0], bh[g2][1]);
                    mma16816(c[f][g2*2+1], ah[f], bh[g2][2], bh[g2][3]);
                    mma16816(c[f][g2*2+0], ah[f], bl[g2][0], bl[g2][1]);
                    mma16816(c[f][g2*2+1], ah[f], bl[g2][2], bl[g2][3]);
                    mma16816(c[f][g2*2+0], al[f], bh[g2][0], bh[g2][1]);
                    mma16816(c[f][g2*2+1], al[f], bh[g2][2], bh[g2][3]);
                }
        }
    }
#undef W_LOAD

    const float m = log1pf(expf(m_raw[0]));
    const float omm = 1.0f - m;
#pragma unroll
    for (int f = 0; f < 4; f++)
#pragma unroll
        for (int g = 0; g < 4; g++)
#pragma unroll
            for (int h = 0; h < 2; h++) {
                const int i = i0 + wm + f * 16 + h * 8 + (l >> 2);
                const int j = j0 + wn + g * 8 + (l & 3) * 2;
                float2 sij = *(const float2*)&S[(long)i * NN + j];
                float w0 = -c[f][g][h*2+0] + sij.x - S[(long)j * NN + i];
                float w1 = -c[f][g][h*2+1] + sij.y - S[(long)(j + 1) * NN + i];
                if (i == j) w0 += omm;
                if (i == j + 1) w1 += omm;
                __nv_bfloat16 h0 = __float2bfloat16_rn(w0);
                __nv_bfloat16 h1 = __float2bfloat16_rn(w1);
                *(__nv_bfloat162*)&g_Whi[(long)i * NN + j] = __halves2bfloat162(h0, h1);
                *(__nv_bfloat162*)&g_Wlo[(long)i * NN + j] = __halves2bfloat162(
                    __float2bfloat16_rn(w0 - __bfloat162float(h0)),
                    __float2bfloat16_rn(w1 - __bfloat162float(h1)));
            }
}

#define TMW 64
#define KTW 16
#define PADW 68
__global__ void __launch_bounds__(256) build_vx_kernel(const float* __restrict__ U,
                                                       const float* __restrict__ b,
                                                       const float* __restrict__ x) {
    __shared__ __align__(16) float Us[KTW][PADW];
    __shared__ __align__(16) float Xs[KTW][PADW];
    const int i0 = blockIdx.x * TMW, j0 = blockIdx.y * TMW;
    const int tx = threadIdx.x & 15, ty = threadIdx.x >> 4;
    float acc[4][4];
#pragma unroll
    for (int a = 0; a < 4; a++)
#pragma unroll
        for (int cc = 0; cc < 4; cc++) acc[a][cc] = 0.0f;
    for (int k0 = 0; k0 < DD; k0 += KTW) {
#pragma unroll
        for (int t = threadIdx.x; t < KTW * TMW; t += 256) {
            int rr = t >> 4, cc = t & 15;
            Us[cc][rr] = U[(i0 + rr) * DD + k0 + cc];
            Xs[cc][rr] = x[(j0 + rr) * DD + k0 + cc];
        }
        __syncthreads();
#pragma unroll
        for (int k = 0; k < KTW; k++) {
            float4 av = *(const float4*)&Us[k][ty * 4];
            float4 bv = *(const float4*)&Xs[k][tx * 4];
            float am[4] = {av.x, av.y, av.z, av.w};
            float bn[4] = {bv.x, bv.y, bv.z, bv.w};
#pragma unroll
            for (int mi = 0; mi < 4; mi++)
#pragma unroll
                for (int ni = 0; ni < 4; ni++) acc[mi][ni] += am[mi] * bn[ni];
        }
        __syncthreads();
    }
#pragma unroll
    for (int mi = 0; mi < 4; mi++) {
        const int i = i0 + ty * 4 + mi;
        const float bi = b[i];
#pragma unroll
        for (int ni = 0; ni < 4; ni++)
            g_Vx[i * BB + j0 + tx * 4 + ni] = acc[mi][ni] + bi;
    }
}

__device__ __forceinline__ void grid_barrier(unsigned& gen) {
    __syncthreads();
    if (threadIdx.x == 0) {
        gen++;
        __threadfence();
        unsigned prev = atomicAdd(&g_arrive, 1u);
        if (prev == SB - 1) {
            atomicExch(&g_arrive, 0u);
            __threadfence();
            atomicExch(&g_release, gen);
        } else {
            while (*(volatile unsigned*)&g_release < gen) { }
            __threadfence();
        }
    }
    __syncthreads();
}

// ---------------- persistent split-K solver, W resident in SMEM -------------
__global__ void __launch_bounds__(256, 1) solve_kernel(float* __restrict__ out) {
    extern __shared__ __align__(16) char dsm[];
    const uint32_t raw = smem_u32(dsm);
    const uint32_t sbase = (raw + 127u) & ~127u;
    char* const sptr = dsm + (sbase - raw);
    const uint32_t O_W = sbase;
    const uint32_t O_B = sbase + O_WBYTES;
    char* const bptr = sptr + O_WBYTES;

    __shared__ float sredD[8], sredN[8];

    const int tid = threadIdx.x, l = tid & 31, warp = tid >> 5;
    const int bm = blockIdx.x >> 3;       // 0..15 m-tile
    const int ks = blockIdx.x & 7;        // 0..7 k-split
    const int i0 = bm * MT;
    const int kbase = ks * KS;
    const int wm = (warp >> 1) * 32;      // 0..96
    const int wn = (warp & 1) * 128;      // 0 / 128
    const int r7 = l & 7;
    const int selA = (l >> 4) & 1, rA8 = ((l >> 3) & 1) * 8;
    const int selB = (l >> 3) & 1, rB8 = ((l >> 4) & 1) * 8;

    // ---- load resident W chunk (once) ----
#pragma unroll
    for (int r = 0; r < 32; r++) {
        const int idx = tid + r * 256;            // 0..8191
        const int prec = idx >> 12;               // 0=hi 1=lo
        const int rem = idx & 4095;
        const int m = rem >> 5, kc = rem & 31;    // kc: 16B chunk (k8)
        const __nv_bfloat16* src =
            (prec ? g_Wlo : g_Whi) + (long)(i0 + m) * NN + kbase + kc * 8;
        const uint32_t dst = O_W + (uint32_t)prec * 65536u + (uint32_t)(kc >> 3) * 16384u +
                             (uint32_t)m * 128u + ((uint32_t)((kc & 7) ^ (m & 7)) << 4);
        cp16(dst, src);
    }
    CP_COMMIT(); CP_WAIT(0); __syncthreads();

    // epilogue ownership: row erow, 16 batch cols at jcol
    const int erow = i0 + (tid >> 1);
    const int jcol = ks * 32 + (tid & 1) * 16;

    unsigned gen = 0;
    int cur = 0, it = 0;

#define B_LOAD(s, zhp, zlp) do {                                              \
    const uint32_t bst_ = O_B + (uint32_t)((s) & 1) * BSTG;                   \
    _Pragma("unroll")                                                         \
    for (int r_ = 0; r_ < 8; r_++) {                                          \
        const int idx_ = tid + r_ * 256;          /* 0..2047 */               \
        const int prec_ = idx_ >> 10;                                         \
        const int rem_ = idx_ & 1023;                                         \
        const int j_ = rem_ >> 2, c_ = rem_ & 3;                              \
        const __nv_bfloat16* src_ =                                           \
            (prec_ ? (zlp) : (zhp)) + (long)j_ * NN + kbase + (s) * 32 + c_ * 8; \
        cp16(bst_ + (uint32_t)prec_ * BPREC + (uint32_t)j_ * 80u +            \
             (uint32_t)c_ * 16u, src_);                                       \
    } } while (0)

    while (1) {
        it++;
        const __nv_bfloat16* __restrict__ zh = g_zbh[cur];
        const __nv_bfloat16* __restrict__ zl = g_zbl[cur];

        float c[2][8][2][4];
#pragma unroll
        for (int f = 0; f < 2; f++)
#pragma unroll
            for (int g = 0; g < 8; g++)
#pragma unroll
                for (int q = 0; q < 8; q++) c[f][g][q >> 2][q & 3] = 0.0f;

        B_LOAD(0, zh, zl); CP_COMMIT();

        for (int s = 0; s < 8; s++) {
            CP_WAIT(0);
            __syncthreads();
            if (s < 7) { B_LOAD(s + 1, zh, zl); }
            CP_COMMIT();

            const uint32_t bst = O_B + (uint32_t)(s & 1) * BSTG;
            const uint32_t wkb = O_W + (uint32_t)(s >> 1) * 16384u;
            const int lc0 = (s & 1) * 4;
#pragma unroll
            for (int h = 0; h < 2; h++) {
                uint32_t ah[2][4], al[2][4];
#pragma unroll
                for (int f = 0; f < 2; f++) {
                    const int rowA = wm + f * 16 + r7 + rA8;
                    const uint32_t lc = (uint32_t)((lc0 + 2 * h + selA) ^ r7) << 4;
                    const uint32_t aaddr = wkb + (uint32_t)rowA * 128u + lc;
                    ldsm4(ah[f], aaddr);
                    ldsm4(al[f], aaddr + 65536u);
                }
#pragma unroll
                for (int g = 0; g < 8; g++) {
                    const int rowB = wn + g * 16 + r7 + rB8;
                    const uint32_t baddr = bst + (uint32_t)rowB * 80u +
                                           (uint32_t)(2 * h + selB) * 16u;
                    uint32_t bh[4], bl[4];
                    ldsm4(bh, baddr);
                    ldsm4(bl, baddr + BPREC);
#pragma unroll
                    for (int f = 0; f < 2; f++) {
                        mma16816(c[f][g][0], ah[f], bh[0], bh[1]);
                        mma16816(c[f][g][1], ah[f], bh[2], bh[3]);
                        mma16816(c[f][g][0], ah[f], bl[0], bl[1]);
                        mma16816(c[f][g][1], ah[f], bl[2], bl[3]);
                        mma16816(c[f][g][0], al[f], bh[0], bh[1]);
                        mma16816(c[f][g][1], al[f], bh[2], bh[3]);
                    }
                }
            }
        }

        // ---- write fp32 partials ----
        {
            float* const pb = g_part + (long)blockIdx.x * (MT * BB);
#pragma unroll
            for (int f = 0; f < 2; f++)
#pragma unroll
                for (int g = 0; g < 8; g++)
#pragma unroll
                    for (int n8 = 0; n8 < 2; n8++) {
                        const int row = wm + f * 16 + (l >> 2);
                        const int col = wn + g * 16 + n8 * 8 + (l & 3) * 2;
                        float2 v0, v1;
                        v0.x = c[f][g][n8][0]; v0.y = c[f][g][n8][1];
                        v1.x = c[f][g][n8][2]; v1.y = c[f][g][n8][3];
                        *(float2*)&pb[row * BB + col] = v0;
                        *(float2*)&pb[(row + 8) * BB + col] = v1;
                    }
        }

        grid_barrier(gen);

        // ---- epilogue: reduce 8 partials, relu update, split writes ----
        float acc[16];
#pragma unroll
        for (int t = 0; t < 16; t++) acc[t] = 0.0f;
        {
            const int roff = (tid >> 1) * BB + (ks * 32 + (tid & 1) * 16);
#pragma unroll
            for (int p = 0; p < 8; p++) {
                const float* pp = g_part + (long)(bm * 8 + p) * (MT * BB) + roff;
#pragma unroll
                for (int q = 0; q < 4; q++) {
                    float4 v = *(const float4*)&pp[q * 4];
                    acc[q * 4 + 0] += v.x; acc[q * 4 + 1] += v.y;
                    acc[q * 4 + 2] += v.z; acc[q * 4 + 3] += v.w;
                }
            }
        }
        float d2 = 0.0f, n2 = 0.0f;
        {
            float* const zfp = g_zf + (long)erow * BB + jcol;
            const float* const vxp = g_Vx + (long)erow * BB + jcol;
            const int iloc = tid >> 1;
            const int jbase = (tid & 1) * 16;
#pragma unroll
            for (int t = 0; t < 16; t++) {
                const float zv = zfp[t];
                float v = 0.9f * zv + 0.1f * (acc[t] + vxp[t]);
                float r = v > 0.0f ? v : 0.0f;
                zfp[t] = r;
                const float dd = r - zv;
                d2 += dd * dd;
                n2 += zv * zv;
                __nv_bfloat16 hi = __float2bfloat16_rn(r);
                __nv_bfloat16 lo = __float2bfloat16_rn(r - __bfloat162float(hi));
                const int jloc = jbase + t;
                *(__nv_bfloat16*)(bptr + jloc * 256 + iloc * 2) = hi;
                *(__nv_bfloat16*)(bptr + 8192 + jloc * 256 + iloc * 2) = lo;
            }
        }
        __syncthreads();
        {
            __nv_bfloat16* const zhn = g_zbh[cur ^ 1];
            __nv_bfloat16* const zln = g_zbl[cur ^ 1];
#pragma unroll
            for (int r = 0; r < 2; r++) {
                const int idx = tid + r * 256;      // 0..511
                const int row = idx >> 4, ch = idx & 15;
                const long go = (long)(ks * 32 + row) * NN + i0 + ch * 8;
                *(uint4*)&zhn[go] = *(const uint4*)(bptr + row * 256 + ch * 16);
                *(uint4*)&zln[go] = *(const uint4*)(bptr + 8192 + row * 256 + ch * 16);
            }
        }
#pragma unroll
        for (int off = 16; off; off >>= 1) {
            d2 += __shfl_xor_sync(0xffffffffu, d2, off);
            n2 += __shfl_xor_sync(0xffffffffu, n2, off);
        }
        if (l == 0) { sredD[warp] = d2; sredN[warp] = n2; }
        __syncthreads();
        const int nb = it % 3;
        if (tid == 0) {
            double Dd = 0.0, Nd = 0.0;
#pragma unroll
            for (int w = 0; w < 8; w++) { Dd += (double)sredD[w]; Nd += (double)sredN[w]; }
            atomicAdd(&g_nd[nb][0], Dd);
            atomicAdd(&g_nd[nb][1], Nd);
        }

        grid_barrier(gen);

        const double Dt = *(volatile double*)&g_nd[nb][0];
        const double Nt = *(volatile double*)&g_nd[nb][1];
        const double err = sqrt(Dt) / (sqrt(Nt) + 1e-12);
        if (blockIdx.x == 0 && tid == 0) {
            const int rb = (it + 2) % 3;
            *(volatile double*)&g_nd[rb][0] = 0.0;
            *(volatile double*)&g_nd[rb][1] = 0.0;
            __threadfence();
        }
        cur ^= 1;
        if (it >= MAXIT || err < 1e-4) break;
    }
#undef B_LOAD

    // final: copy owned fp32 z to out
    {
        const float* const zfp = g_zf + (long)erow * BB + jcol;
        float* const op = out + (long)erow * BB + jcol;
#pragma unroll
        for (int q = 0; q < 4; q++)
            *(float4*)&op[q * 4] = *(const float4*)&zfp[q * 4];
    }
}

extern "C" void kernel_launch(void* const* d_in, const int* in_sizes, int n_in,
                              void* d_out, int out_size) {
    const float* A     = (const float*)d_in[0];
    const float* S     = (const float*)d_in[1];
    const float* m_raw = (const float*)d_in[2];
    const float* U     = (const float*)d_in[3];
    const float* b     = (const float*)d_in[4];
    const float* x     = (const float*)d_in[5];
    float* out = (float*)d_out;

    cudaFuncSetAttribute(solve_kernel, cudaFuncAttributeMaxDynamicSharedMemorySize, DYN_SMEM);
    cudaFuncSetAttribute(build_w_mma_kernel, cudaFuncAttributeMaxDynamicSharedMemorySize, WDYN);

    init_kernel<<<(BB * NN + 255) / 256, 256>>>();
    dim3 gt(NN / 32, NN / 32);
    split_at_kernel<<<gt, 256>>>(A);
    dim3 gw(NN / 128, NN / 128);
    build_w_mma_kernel<<<gw, 256, WDYN>>>(S, m_raw);
    dim3 gv(NN / TMW, BB / TMW);
    build_vx_kernel<<<gv, 256>>>(U, b, x);
    solve_kernel<<<SB, 256, DYN_SMEM>>>(out);
}